// round 12
// baseline (speedup 1.0000x reference)
#include <cuda_runtime.h>
#include <cuda_bf16.h>

#define NN 50000
#define NE 800000
#define DD 128
#define SCAN_BS 512
#define NBLK ((NN + SCAN_BS - 1) / SCAN_BS)   // 98
#define NCHUNK 4
#define CHUNK 12544                            // 128-aligned; last = 50000-3*12544=12368

// ---------------- scratch (static __device__; referenced ONLY in device code) ----
__device__ int   g_is64;
__device__ int   g_cnt[NN];
__device__ float g_deg[NN];
__device__ int   g_offs[NN + 1];
__device__ int   g_pos[NN];
__device__ int   g_bsum[NBLK];
__device__ int   g_src[NE];
__device__ float g_wcsr[NE];         // full GCN norm per CSR slot
__device__ float g_dis[NN];
__device__ float g_h[NN * DD];       // layer-1 GEMM out (X@W1)
__device__ float g_h2[NN * DD];      // layer-2 GEMM out (relu(a1)@W2)
__device__ float g_a1[NN * DD];
__device__ float g_Wh[2][DD * 136];
__device__ float g_Wl[2][DD * 136];

// ---------------- prep0: detect dtype + zero cnt/deg ----------------
__global__ void k_prep0(const void* ei) {
    int i = blockIdx.x * blockDim.x + threadIdx.x;
    if (i < NN) { g_cnt[i] = 0; g_deg[i] = 0.0f; }
    if (blockIdx.x == 0) {
        __shared__ int bad;
        if (threadIdx.x == 0) bad = 0;
        __syncthreads();
        const long long* p = (const long long*)ei;
        for (int t = threadIdx.x; t < 1024; t += blockDim.x) {
            long long v = p[t];
            if (v < 0 || v >= NN) atomicOr(&bad, 1);
        }
        __syncthreads();
        if (threadIdx.x == 0) g_is64 = bad ? 0 : 1;
    }
}

// ---------------- count + weighted degree ----------------
__global__ void k_count(const void* ei, const float* __restrict__ ew) {
    int e = blockIdx.x * blockDim.x + threadIdx.x;
    if (e < NE) {
        int c = g_is64 ? (int)((const long long*)ei)[NE + e]
                       : ((const int*)ei)[NE + e];
        atomicAdd(&g_cnt[c], 1);
        atomicAdd(&g_deg[c], ew[e]);
    }
}

// ---------------- scan stage 1 ----------------
__global__ __launch_bounds__(SCAN_BS) void k_scan1() {
    int i = blockIdx.x * SCAN_BS + threadIdx.x;
    int lane = threadIdx.x & 31, wid = threadIdx.x >> 5;
    int v = (i < NN) ? g_cnt[i] : 0;
    int x = v;
#pragma unroll
    for (int o = 1; o < 32; o <<= 1) {
        int t = __shfl_up_sync(0xffffffffu, x, o);
        if (lane >= o) x += t;
    }
    __shared__ int wsum[16];
    if (lane == 31) wsum[wid] = x;
    __syncthreads();
    if (wid == 0) {
        int s = (lane < 16) ? wsum[lane] : 0;
#pragma unroll
        for (int o = 1; o < 16; o <<= 1) {
            int t = __shfl_up_sync(0xffffffffu, s, o);
            if (lane >= o) s += t;
        }
        if (lane < 16) wsum[lane] = s;
    }
    __syncthreads();
    int base = (wid > 0) ? wsum[wid - 1] : 0;
    if (i < NN) g_offs[i] = base + x - v;
    if (threadIdx.x == SCAN_BS - 1) g_bsum[blockIdx.x] = base + x;
}

// ---------------- scan stage 2 (fused add-back + dis) ----------------
__global__ __launch_bounds__(SCAN_BS) void k_scan3() {
    __shared__ int sbase;
    if (threadIdx.x < 32) {
        int p = 0;
        for (int j = threadIdx.x; j < blockIdx.x; j += 32) p += g_bsum[j];
#pragma unroll
        for (int o = 16; o > 0; o >>= 1) p += __shfl_down_sync(0xffffffffu, p, o);
        if (threadIdx.x == 0) sbase = p;
    }
    __syncthreads();
    int i = blockIdx.x * SCAN_BS + threadIdx.x;
    if (i < NN) {
        int off = g_offs[i] + sbase;
        g_offs[i] = off;
        g_pos[i] = off;
        g_dis[i] = rsqrtf(1.0f + g_deg[i]);
    }
    if (i == 0) g_offs[NN] = NE;
}

// ---------------- CSR fill with full norm ----------------
__global__ void k_fill(const void* ei, const float* __restrict__ ew) {
    int e = blockIdx.x * blockDim.x + threadIdx.x;
    if (e < NE) {
        int r, c;
        if (g_is64) {
            const long long* p = (const long long*)ei;
            r = (int)p[e];
            c = (int)p[NE + e];
        } else {
            const int* p = (const int*)ei;
            r = p[e];
            c = p[NE + e];
        }
        float nr = g_dis[r] * ew[e] * g_dis[c];
        int idx = atomicAdd(&g_pos[c], 1);
        g_src[idx] = r;
        g_wcsr[idx] = nr;
    }
}

// ---------------- tf32 helpers ----------------
__device__ __forceinline__ void split_tf32(float v, float& hi, float& lo) {
    unsigned uh;
    asm("cvt.rna.tf32.f32 %0, %1;" : "=r"(uh) : "f"(v));
    hi = __uint_as_float(uh);
    float r = v - hi;
    unsigned ul;
    asm("cvt.rna.tf32.f32 %0, %1;" : "=r"(ul) : "f"(r));
    lo = __uint_as_float(ul);
}

__device__ __forceinline__ void mma_tf32(float* d, const unsigned* a, const unsigned* b) {
    asm volatile("mma.sync.aligned.m16n8k8.row.col.f32.tf32.tf32.f32 "
                 "{%0,%1,%2,%3}, {%4,%5,%6,%7}, {%8,%9}, {%0,%1,%2,%3};"
                 : "+f"(d[0]), "+f"(d[1]), "+f"(d[2]), "+f"(d[3])
                 : "r"(a[0]), "r"(a[1]), "r"(a[2]), "r"(a[3]), "r"(b[0]), "r"(b[1]));
}

// ---------------- W pre-split ----------------
__global__ void k_wsplit(const float* __restrict__ W1, const float* __restrict__ W2) {
    int f = blockIdx.x * blockDim.x + threadIdx.x;
    if (f >= 2 * DD * 32) return;
    int m = f >> 12;
    int rem = f & 4095;
    int k = rem >> 5;
    int c4 = rem & 31;
    const float* W = m ? W2 : W1;
    float4 v = *reinterpret_cast<const float4*>(&W[k * DD + c4 * 4]);
    float h0, l0, h1, l1, h2, l2, h3, l3;
    split_tf32(v.x, h0, l0); split_tf32(v.y, h1, l1);
    split_tf32(v.z, h2, l2); split_tf32(v.w, h3, l3);
    int o = k * 136 + c4 * 4;
    *reinterpret_cast<float4*>(&g_Wh[m][o]) = make_float4(h0, h1, h2, h3);
    *reinterpret_cast<float4*>(&g_Wl[m][o]) = make_float4(l0, l1, l2, l3);
}

// ---------------- GEMM (tf32 split), row-chunked: Hout[base..] = X @ W[layer] ----
// layer 0: X = Xext,  Hout = g_h ;  layer 1: X = g_a1 (relu), Hout = g_h2
template<bool RELU>
__global__ __launch_bounds__(256) void k_gemm(const float* __restrict__ Xext, int layer,
                                              int rbase) {
    const float* __restrict__ X = (Xext != nullptr) ? Xext : (const float*)g_a1;
    float* __restrict__ Hout = (layer == 0) ? (float*)g_h : (float*)g_h2;
    const float* __restrict__ Wh = g_Wh[layer];
    const float* __restrict__ Wl = g_Wl[layer];

    __shared__ float sXh[128][36], sXl[128][36];
    __shared__ float sWh[32][136], sWl[32][136];

    const int tid = threadIdx.x;
    const int wid = tid >> 5, lane = tid & 31;
    const int g = lane >> 2, tig = lane & 3;
    const int warp_m = wid & 3, warp_n = wid >> 2;
    const int bm0 = rbase + blockIdx.x * 128;

    float acc[2][8][4];
#pragma unroll
    for (int mt = 0; mt < 2; mt++)
#pragma unroll
        for (int nt = 0; nt < 8; nt++)
#pragma unroll
            for (int c = 0; c < 4; c++) acc[mt][nt][c] = 0.0f;

    for (int k0 = 0; k0 < DD; k0 += 32) {
#pragma unroll
        for (int i = 0; i < 4; i++) {
            int f = tid + i * 256;
            int r = f >> 3, c4 = f & 7;
            int row = bm0 + r;
            float4 v = make_float4(0.f, 0.f, 0.f, 0.f);
            if (row < NN) v = *reinterpret_cast<const float4*>(&X[row * DD + k0 + c4 * 4]);
            if (RELU) {
                v.x = fmaxf(v.x, 0.f); v.y = fmaxf(v.y, 0.f);
                v.z = fmaxf(v.z, 0.f); v.w = fmaxf(v.w, 0.f);
            }
            float h0, l0, h1, l1, h2, l2, h3, l3;
            split_tf32(v.x, h0, l0); split_tf32(v.y, h1, l1);
            split_tf32(v.z, h2, l2); split_tf32(v.w, h3, l3);
            int c = c4 * 4;
            sXh[r][c] = h0; sXh[r][c + 1] = h1; sXh[r][c + 2] = h2; sXh[r][c + 3] = h3;
            sXl[r][c] = l0; sXl[r][c + 1] = l1; sXl[r][c + 2] = l2; sXl[r][c + 3] = l3;
        }
#pragma unroll
        for (int i = 0; i < 4; i++) {
            int f = tid + i * 256;
            int k = f >> 5, c4 = f & 31;
            int o = (k0 + k) * 136 + c4 * 4;
            *reinterpret_cast<float4*>(&sWh[k][c4 * 4]) =
                *reinterpret_cast<const float4*>(&Wh[o]);
            *reinterpret_cast<float4*>(&sWl[k][c4 * 4]) =
                *reinterpret_cast<const float4*>(&Wl[o]);
        }
        __syncthreads();

#pragma unroll
        for (int kk = 0; kk < 32; kk += 8) {
            unsigned Ah[2][4], Al[2][4], Bh[8][2], Bl[8][2];
#pragma unroll
            for (int mt = 0; mt < 2; mt++) {
                int r0 = warp_m * 32 + mt * 16 + g;
                Ah[mt][0] = __float_as_uint(sXh[r0][kk + tig]);
                Ah[mt][1] = __float_as_uint(sXh[r0 + 8][kk + tig]);
                Ah[mt][2] = __float_as_uint(sXh[r0][kk + tig + 4]);
                Ah[mt][3] = __float_as_uint(sXh[r0 + 8][kk + tig + 4]);
                Al[mt][0] = __float_as_uint(sXl[r0][kk + tig]);
                Al[mt][1] = __float_as_uint(sXl[r0 + 8][kk + tig]);
                Al[mt][2] = __float_as_uint(sXl[r0][kk + tig + 4]);
                Al[mt][3] = __float_as_uint(sXl[r0 + 8][kk + tig + 4]);
            }
#pragma unroll
            for (int nt = 0; nt < 8; nt++) {
                int n = warp_n * 64 + nt * 8 + g;
                Bh[nt][0] = __float_as_uint(sWh[kk + tig][n]);
                Bh[nt][1] = __float_as_uint(sWh[kk + tig + 4][n]);
                Bl[nt][0] = __float_as_uint(sWl[kk + tig][n]);
                Bl[nt][1] = __float_as_uint(sWl[kk + tig + 4][n]);
            }
#pragma unroll
            for (int mt = 0; mt < 2; mt++)
#pragma unroll
                for (int nt = 0; nt < 8; nt++) {
                    mma_tf32(acc[mt][nt], Ah[mt], Bh[nt]);
                    mma_tf32(acc[mt][nt], Ah[mt], Bl[nt]);
                    mma_tf32(acc[mt][nt], Al[mt], Bh[nt]);
                }
        }
        __syncthreads();
    }

#pragma unroll
    for (int mt = 0; mt < 2; mt++) {
        int r0 = bm0 + warp_m * 32 + mt * 16 + g;
        int r1 = r0 + 8;
#pragma unroll
        for (int nt = 0; nt < 8; nt++) {
            int col = warp_n * 64 + nt * 8 + tig * 2;
            if (r0 < NN)
                *reinterpret_cast<float2*>(&Hout[r0 * DD + col]) =
                    make_float2(acc[mt][nt][0], acc[mt][nt][1]);
            if (r1 < NN)
                *reinterpret_cast<float2*>(&Hout[r1 * DD + col]) =
                    make_float2(acc[mt][nt][2], acc[mt][nt][3]);
        }
    }
}

// ---------------- aggregate (node-chunked): out = b + dis^2*H_i + sum nrm*H_src --
// layer selects which GEMM output buffer to gather from (0 -> g_h, 1 -> g_h2).
__global__ __launch_bounds__(256) void k_agg(const float* __restrict__ b,
                                             float* __restrict__ outext,
                                             int layer, int nbase, int ncount) {
    float* __restrict__ out = (outext != nullptr) ? outext : (float*)g_a1;
    const float* __restrict__ h = (layer == 0) ? (const float*)g_h : (const float*)g_h2;

    int node = nbase + blockIdx.x * 8 + (threadIdx.x >> 5);
    int lane = threadIdx.x & 31;
    if (node >= nbase + ncount || node >= NN) return;

    float s = g_dis[node];
    float s2 = s * s;
    float4 hv = *reinterpret_cast<const float4*>(&h[node * DD + lane * 4]);
    float ax = s2 * hv.x, ay = s2 * hv.y, az = s2 * hv.z, aw = s2 * hv.w;

    int j = g_offs[node];
    int end = g_offs[node + 1];

    for (; j + 3 < end; j += 4) {
        int s0 = g_src[j],     s1 = g_src[j + 1];
        int sA = g_src[j + 2], sB = g_src[j + 3];
        float n0 = g_wcsr[j],     n1 = g_wcsr[j + 1];
        float n2 = g_wcsr[j + 2], n3 = g_wcsr[j + 3];
        float4 v0 = *reinterpret_cast<const float4*>(&h[s0 * DD + lane * 4]);
        float4 v1 = *reinterpret_cast<const float4*>(&h[s1 * DD + lane * 4]);
        float4 v2 = *reinterpret_cast<const float4*>(&h[sA * DD + lane * 4]);
        float4 v3 = *reinterpret_cast<const float4*>(&h[sB * DD + lane * 4]);
        ax += n0 * v0.x + n1 * v1.x + n2 * v2.x + n3 * v3.x;
        ay += n0 * v0.y + n1 * v1.y + n2 * v2.y + n3 * v3.y;
        az += n0 * v0.z + n1 * v1.z + n2 * v2.z + n3 * v3.z;
        aw += n0 * v0.w + n1 * v1.w + n2 * v2.w + n3 * v3.w;
    }
    for (; j < end; j++) {
        int s0 = g_src[j];
        float n0 = g_wcsr[j];
        float4 v0 = *reinterpret_cast<const float4*>(&h[s0 * DD + lane * 4]);
        ax += n0 * v0.x; ay += n0 * v0.y; az += n0 * v0.z; aw += n0 * v0.w;
    }

    float4 bv = *reinterpret_cast<const float4*>(&b[lane * 4]);
    *reinterpret_cast<float4*>(&out[node * DD + lane * 4]) =
        make_float4(bv.x + ax, bv.y + ay, bv.z + az, bv.w + aw);
}

// ---------------- launch: prep || (wsplit+gemm1); then agg1/gemm2 chunk pipeline --
extern "C" void kernel_launch(void* const* d_in, const int* in_sizes, int n_in,
                              void* d_out, int out_size) {
    const float* x  = (const float*)d_in[0];
    const void*  ei = d_in[1];
    const float* ew = (const float*)d_in[2];
    const float* W1 = (const float*)d_in[3];
    const float* b1 = (const float*)d_in[4];
    const float* W2 = (const float*)d_in[5];
    const float* b2 = (const float*)d_in[6];
    float* out = (float*)d_out;

    static cudaStream_t sB = nullptr;
    static cudaEvent_t evFork = nullptr, evPrep = nullptr;
    static cudaEvent_t evA[NCHUNK], evG[NCHUNK];
    if (sB == nullptr) {
        cudaStreamCreateWithFlags(&sB, cudaStreamNonBlocking);
        cudaEventCreateWithFlags(&evFork, cudaEventDisableTiming);
        cudaEventCreateWithFlags(&evPrep, cudaEventDisableTiming);
        for (int c = 0; c < NCHUNK; c++) {
            cudaEventCreateWithFlags(&evA[c], cudaEventDisableTiming);
            cudaEventCreateWithFlags(&evG[c], cudaEventDisableTiming);
        }
    }

    const int T = 256;
    const int gN = (NN + T - 1) / T;
    const int gE = (NE + T - 1) / T;
    const int gG = (NN + 127) / 128;
    const int gA = (NN + 7) / 8;
    const int gW = (2 * DD * 32 + T - 1) / T;

    // fork: prep chain on sB
    cudaEventRecord(evFork, 0);
    cudaStreamWaitEvent(sB, evFork, 0);
    k_prep0<<<gN, T, 0, sB>>>(ei);
    k_count<<<gE, T, 0, sB>>>(ei, ew);
    k_scan1<<<NBLK, SCAN_BS, 0, sB>>>();
    k_scan3<<<NBLK, SCAN_BS, 0, sB>>>();
    k_fill<<<gE, T, 0, sB>>>(ei, ew);
    cudaEventRecord(evPrep, sB);

    // concurrent on stream0: weight split + full layer-1 GEMM -> g_h
    k_wsplit<<<gW, T>>>(W1, W2);
    k_gemm<false><<<gG, 256>>>(x, 0, 0);

    // join prep, then chunked agg1 (reads g_h) -> gemm2 (writes g_h2) pipeline
    cudaStreamWaitEvent(0, evPrep, 0);
    for (int c = 0; c < NCHUNK; c++) {
        int base = c * CHUNK;
        int count = (c == NCHUNK - 1) ? (NN - base) : CHUNK;
        int ga = (count + 7) / 8;
        int gg = (count + 127) / 128;
        k_agg<<<ga, T>>>(b1, nullptr, 0, base, count);
        cudaEventRecord(evA[c], 0);
        cudaStreamWaitEvent(sB, evA[c], 0);
        k_gemm<true><<<gg, 256, 0, sB>>>(nullptr, 1, base);
        cudaEventRecord(evG[c], sB);
    }
    for (int c = 0; c < NCHUNK; c++) cudaStreamWaitEvent(0, evG[c], 0);
    k_agg<<<gA, T>>>(b2, out, 1, 0, NN);
}

// round 14
// speedup vs baseline: 1.1598x; 1.1598x over previous
#include <cuda_runtime.h>
#include <cuda_bf16.h>
#include <cuda_fp16.h>

#define NN 50000
#define NE 800000
#define DD 128
#define SCAN_BS 512
#define NBLK ((NN + SCAN_BS - 1) / SCAN_BS)   // 98

// ---------------- scratch (static __device__; referenced ONLY in device code) ----
__device__ int     g_is64;
__device__ int     g_cnt[NN];
__device__ float   g_deg[NN];
__device__ int     g_offs[NN + 1];
__device__ int     g_pos[NN];
__device__ int     g_bsum[NBLK];
__device__ int     g_src[NE];
__device__ float   g_wcsr[NE];       // full GCN norm per CSR slot
__device__ float   g_dis[NN];
__device__ __half2 g_hh[NN * 64];    // layer-1 GEMM out (X@W1), fp16
__device__ __half2 g_hh2[NN * 64];   // layer-2 GEMM out, fp16
__device__ float   g_a1[NN * DD];    // layer-1 aggregate (fp32, GEMM-2 input)
__device__ float   g_Wh[2][DD * 136];
__device__ float   g_Wl[2][DD * 136];

// ---------------- prep0: detect dtype + zero cnt/deg ----------------
__global__ void k_prep0(const void* ei) {
    int i = blockIdx.x * blockDim.x + threadIdx.x;
    if (i < NN) { g_cnt[i] = 0; g_deg[i] = 0.0f; }
    if (blockIdx.x == 0) {
        __shared__ int bad;
        if (threadIdx.x == 0) bad = 0;
        __syncthreads();
        const long long* p = (const long long*)ei;
        for (int t = threadIdx.x; t < 1024; t += blockDim.x) {
            long long v = p[t];
            if (v < 0 || v >= NN) atomicOr(&bad, 1);
        }
        __syncthreads();
        if (threadIdx.x == 0) g_is64 = bad ? 0 : 1;
    }
}

// ---------------- count + weighted degree ----------------
__global__ void k_count(const void* ei, const float* __restrict__ ew) {
    int e = blockIdx.x * blockDim.x + threadIdx.x;
    if (e < NE) {
        int c = g_is64 ? (int)((const long long*)ei)[NE + e]
                       : ((const int*)ei)[NE + e];
        atomicAdd(&g_cnt[c], 1);
        atomicAdd(&g_deg[c], ew[e]);
    }
}

// ---------------- scan stage 1 ----------------
__global__ __launch_bounds__(SCAN_BS) void k_scan1() {
    int i = blockIdx.x * SCAN_BS + threadIdx.x;
    int lane = threadIdx.x & 31, wid = threadIdx.x >> 5;
    int v = (i < NN) ? g_cnt[i] : 0;
    int x = v;
#pragma unroll
    for (int o = 1; o < 32; o <<= 1) {
        int t = __shfl_up_sync(0xffffffffu, x, o);
        if (lane >= o) x += t;
    }
    __shared__ int wsum[16];
    if (lane == 31) wsum[wid] = x;
    __syncthreads();
    if (wid == 0) {
        int s = (lane < 16) ? wsum[lane] : 0;
#pragma unroll
        for (int o = 1; o < 16; o <<= 1) {
            int t = __shfl_up_sync(0xffffffffu, s, o);
            if (lane >= o) s += t;
        }
        if (lane < 16) wsum[lane] = s;
    }
    __syncthreads();
    int base = (wid > 0) ? wsum[wid - 1] : 0;
    if (i < NN) g_offs[i] = base + x - v;
    if (threadIdx.x == SCAN_BS - 1) g_bsum[blockIdx.x] = base + x;
}

// ---------------- scan stage 2 (fused add-back + dis) ----------------
__global__ __launch_bounds__(SCAN_BS) void k_scan3() {
    __shared__ int sbase;
    if (threadIdx.x < 32) {
        int p = 0;
        for (int j = threadIdx.x; j < blockIdx.x; j += 32) p += g_bsum[j];
#pragma unroll
        for (int o = 16; o > 0; o >>= 1) p += __shfl_down_sync(0xffffffffu, p, o);
        if (threadIdx.x == 0) sbase = p;
    }
    __syncthreads();
    int i = blockIdx.x * SCAN_BS + threadIdx.x;
    if (i < NN) {
        int off = g_offs[i] + sbase;
        g_offs[i] = off;
        g_pos[i] = off;
        g_dis[i] = rsqrtf(1.0f + g_deg[i]);
    }
    if (i == 0) g_offs[NN] = NE;
}

// ---------------- CSR fill with full norm ----------------
__global__ void k_fill(const void* ei, const float* __restrict__ ew) {
    int e = blockIdx.x * blockDim.x + threadIdx.x;
    if (e < NE) {
        int r, c;
        if (g_is64) {
            const long long* p = (const long long*)ei;
            r = (int)p[e];
            c = (int)p[NE + e];
        } else {
            const int* p = (const int*)ei;
            r = p[e];
            c = p[NE + e];
        }
        float nr = g_dis[r] * ew[e] * g_dis[c];
        int idx = atomicAdd(&g_pos[c], 1);
        g_src[idx] = r;
        g_wcsr[idx] = nr;
    }
}

// ---------------- tf32 helpers ----------------
__device__ __forceinline__ void split_tf32(float v, float& hi, float& lo) {
    unsigned uh;
    asm("cvt.rna.tf32.f32 %0, %1;" : "=r"(uh) : "f"(v));
    hi = __uint_as_float(uh);
    float r = v - hi;
    unsigned ul;
    asm("cvt.rna.tf32.f32 %0, %1;" : "=r"(ul) : "f"(r));
    lo = __uint_as_float(ul);
}

__device__ __forceinline__ void mma_tf32(float* d, const unsigned* a, const unsigned* b) {
    asm volatile("mma.sync.aligned.m16n8k8.row.col.f32.tf32.tf32.f32 "
                 "{%0,%1,%2,%3}, {%4,%5,%6,%7}, {%8,%9}, {%0,%1,%2,%3};"
                 : "+f"(d[0]), "+f"(d[1]), "+f"(d[2]), "+f"(d[3])
                 : "r"(a[0]), "r"(a[1]), "r"(a[2]), "r"(a[3]), "r"(b[0]), "r"(b[1]));
}

// ---------------- W pre-split ----------------
__global__ void k_wsplit(const float* __restrict__ W1, const float* __restrict__ W2) {
    int f = blockIdx.x * blockDim.x + threadIdx.x;
    if (f >= 2 * DD * 32) return;
    int m = f >> 12;
    int rem = f & 4095;
    int k = rem >> 5;
    int c4 = rem & 31;
    const float* W = m ? W2 : W1;
    float4 v = *reinterpret_cast<const float4*>(&W[k * DD + c4 * 4]);
    float h0, l0, h1, l1, h2, l2, h3, l3;
    split_tf32(v.x, h0, l0); split_tf32(v.y, h1, l1);
    split_tf32(v.z, h2, l2); split_tf32(v.w, h3, l3);
    int o = k * 136 + c4 * 4;
    *reinterpret_cast<float4*>(&g_Wh[m][o]) = make_float4(h0, h1, h2, h3);
    *reinterpret_cast<float4*>(&g_Wl[m][o]) = make_float4(l0, l1, l2, l3);
}

// ---------------- GEMM (tf32 split): Hout(fp16) = X @ W[layer] ----
// layer 0: X = Xext, Hout = g_hh ;  layer 1: X = g_a1 (relu), Hout = g_hh2
template<bool RELU>
__global__ __launch_bounds__(256) void k_gemm(const float* __restrict__ Xext, int layer) {
    const float* __restrict__ X = (Xext != nullptr) ? Xext : (const float*)g_a1;
    __half2* __restrict__ Hout = (layer == 0) ? (__half2*)g_hh : (__half2*)g_hh2;
    const float* __restrict__ Wh = g_Wh[layer];
    const float* __restrict__ Wl = g_Wl[layer];

    __shared__ float sXh[128][36], sXl[128][36];
    __shared__ float sWh[32][136], sWl[32][136];

    const int tid = threadIdx.x;
    const int wid = tid >> 5, lane = tid & 31;
    const int g = lane >> 2, tig = lane & 3;
    const int warp_m = wid & 3, warp_n = wid >> 2;
    const int bm0 = blockIdx.x * 128;

    float acc[2][8][4];
#pragma unroll
    for (int mt = 0; mt < 2; mt++)
#pragma unroll
        for (int nt = 0; nt < 8; nt++)
#pragma unroll
            for (int c = 0; c < 4; c++) acc[mt][nt][c] = 0.0f;

    for (int k0 = 0; k0 < DD; k0 += 32) {
#pragma unroll
        for (int i = 0; i < 4; i++) {
            int f = tid + i * 256;
            int r = f >> 3, c4 = f & 7;
            int row = bm0 + r;
            float4 v = make_float4(0.f, 0.f, 0.f, 0.f);
            if (row < NN) v = *reinterpret_cast<const float4*>(&X[row * DD + k0 + c4 * 4]);
            if (RELU) {
                v.x = fmaxf(v.x, 0.f); v.y = fmaxf(v.y, 0.f);
                v.z = fmaxf(v.z, 0.f); v.w = fmaxf(v.w, 0.f);
            }
            float h0, l0, h1, l1, h2, l2, h3, l3;
            split_tf32(v.x, h0, l0); split_tf32(v.y, h1, l1);
            split_tf32(v.z, h2, l2); split_tf32(v.w, h3, l3);
            int c = c4 * 4;
            sXh[r][c] = h0; sXh[r][c + 1] = h1; sXh[r][c + 2] = h2; sXh[r][c + 3] = h3;
            sXl[r][c] = l0; sXl[r][c + 1] = l1; sXl[r][c + 2] = l2; sXl[r][c + 3] = l3;
        }
#pragma unroll
        for (int i = 0; i < 4; i++) {
            int f = tid + i * 256;
            int k = f >> 5, c4 = f & 31;
            int o = (k0 + k) * 136 + c4 * 4;
            *reinterpret_cast<float4*>(&sWh[k][c4 * 4]) =
                *reinterpret_cast<const float4*>(&Wh[o]);
            *reinterpret_cast<float4*>(&sWl[k][c4 * 4]) =
                *reinterpret_cast<const float4*>(&Wl[o]);
        }
        __syncthreads();

#pragma unroll
        for (int kk = 0; kk < 32; kk += 8) {
            unsigned Ah[2][4], Al[2][4], Bh[8][2], Bl[8][2];
#pragma unroll
            for (int mt = 0; mt < 2; mt++) {
                int r0 = warp_m * 32 + mt * 16 + g;
                Ah[mt][0] = __float_as_uint(sXh[r0][kk + tig]);
                Ah[mt][1] = __float_as_uint(sXh[r0 + 8][kk + tig]);
                Ah[mt][2] = __float_as_uint(sXh[r0][kk + tig + 4]);
                Ah[mt][3] = __float_as_uint(sXh[r0 + 8][kk + tig + 4]);
                Al[mt][0] = __float_as_uint(sXl[r0][kk + tig]);
                Al[mt][1] = __float_as_uint(sXl[r0 + 8][kk + tig]);
                Al[mt][2] = __float_as_uint(sXl[r0][kk + tig + 4]);
                Al[mt][3] = __float_as_uint(sXl[r0 + 8][kk + tig + 4]);
            }
#pragma unroll
            for (int nt = 0; nt < 8; nt++) {
                int n = warp_n * 64 + nt * 8 + g;
                Bh[nt][0] = __float_as_uint(sWh[kk + tig][n]);
                Bh[nt][1] = __float_as_uint(sWh[kk + tig + 4][n]);
                Bl[nt][0] = __float_as_uint(sWl[kk + tig][n]);
                Bl[nt][1] = __float_as_uint(sWl[kk + tig + 4][n]);
            }
#pragma unroll
            for (int mt = 0; mt < 2; mt++)
#pragma unroll
                for (int nt = 0; nt < 8; nt++) {
                    mma_tf32(acc[mt][nt], Ah[mt], Bh[nt]);
                    mma_tf32(acc[mt][nt], Ah[mt], Bl[nt]);
                    mma_tf32(acc[mt][nt], Al[mt], Bh[nt]);
                }
        }
        __syncthreads();
    }

    // epilogue: convert to fp16, store into [NN][64] half2 layout
#pragma unroll
    for (int mt = 0; mt < 2; mt++) {
        int r0 = bm0 + warp_m * 32 + mt * 16 + g;
        int r1 = r0 + 8;
#pragma unroll
        for (int nt = 0; nt < 8; nt++) {
            int col = warp_n * 64 + nt * 8 + tig * 2;   // even
            int h2i = col >> 1;
            if (r0 < NN)
                Hout[r0 * 64 + h2i] = __floats2half2_rn(acc[mt][nt][0], acc[mt][nt][1]);
            if (r1 < NN)
                Hout[r1 * 64 + h2i] = __floats2half2_rn(acc[mt][nt][2], acc[mt][nt][3]);
        }
    }
}

// ---------------- aggregate: warp/node CSR gather from fp16 h ----------------
// out = b + dis^2*H_i + sum nrm_j*H_src   (fp32 accumulate)
__global__ __launch_bounds__(256) void k_agg(const float* __restrict__ b,
                                             float* __restrict__ outext, int layer) {
    float* __restrict__ out = (outext != nullptr) ? outext : (float*)g_a1;
    const __half2* __restrict__ h =
        (layer == 0) ? (const __half2*)g_hh : (const __half2*)g_hh2;

    int node = blockIdx.x * 8 + (threadIdx.x >> 5);
    int lane = threadIdx.x & 31;
    if (node >= NN) return;

    // lane covers 4 cols = 2 half2 = 8 bytes
    const int hoff = lane * 2;

    float s = g_dis[node];
    float s2 = s * s;
    uint2 uself = *reinterpret_cast<const uint2*>(&h[node * 64 + hoff]);
    float2 p0 = __half22float2(*reinterpret_cast<const __half2*>(&uself.x));
    float2 p1 = __half22float2(*reinterpret_cast<const __half2*>(&uself.y));
    float ax = s2 * p0.x, ay = s2 * p0.y, az = s2 * p1.x, aw = s2 * p1.y;

    int j = g_offs[node];
    int end = g_offs[node + 1];

    for (; j + 3 < end; j += 4) {
        int s0 = g_src[j],     s1 = g_src[j + 1];
        int sA = g_src[j + 2], sB = g_src[j + 3];
        float n0 = g_wcsr[j],     n1 = g_wcsr[j + 1];
        float n2 = g_wcsr[j + 2], n3 = g_wcsr[j + 3];
        uint2 u0 = *reinterpret_cast<const uint2*>(&h[s0 * 64 + hoff]);
        uint2 u1 = *reinterpret_cast<const uint2*>(&h[s1 * 64 + hoff]);
        uint2 u2 = *reinterpret_cast<const uint2*>(&h[sA * 64 + hoff]);
        uint2 u3 = *reinterpret_cast<const uint2*>(&h[sB * 64 + hoff]);
        float2 a0 = __half22float2(*reinterpret_cast<const __half2*>(&u0.x));
        float2 b0 = __half22float2(*reinterpret_cast<const __half2*>(&u0.y));
        float2 a1 = __half22float2(*reinterpret_cast<const __half2*>(&u1.x));
        float2 b1 = __half22float2(*reinterpret_cast<const __half2*>(&u1.y));
        float2 a2 = __half22float2(*reinterpret_cast<const __half2*>(&u2.x));
        float2 b2 = __half22float2(*reinterpret_cast<const __half2*>(&u2.y));
        float2 a3 = __half22float2(*reinterpret_cast<const __half2*>(&u3.x));
        float2 b3 = __half22float2(*reinterpret_cast<const __half2*>(&u3.y));
        ax += n0 * a0.x + n1 * a1.x + n2 * a2.x + n3 * a3.x;
        ay += n0 * a0.y + n1 * a1.y + n2 * a2.y + n3 * a3.y;
        az += n0 * b0.x + n1 * b1.x + n2 * b2.x + n3 * b3.x;
        aw += n0 * b0.y + n1 * b1.y + n2 * b2.y + n3 * b3.y;
    }
    for (; j < end; j++) {
        int s0 = g_src[j];
        float n0 = g_wcsr[j];
        uint2 u0 = *reinterpret_cast<const uint2*>(&h[s0 * 64 + hoff]);
        float2 a0 = __half22float2(*reinterpret_cast<const __half2*>(&u0.x));
        float2 b0 = __half22float2(*reinterpret_cast<const __half2*>(&u0.y));
        ax += n0 * a0.x; ay += n0 * a0.y; az += n0 * b0.x; aw += n0 * b0.y;
    }

    float4 bv = *reinterpret_cast<const float4*>(&b[lane * 4]);
    *reinterpret_cast<float4*>(&out[node * DD + lane * 4]) =
        make_float4(bv.x + ax, bv.y + ay, bv.z + az, bv.w + aw);
}

// ---------------- launch: prep (sB) || wsplit+gemm1 (s0); serial tail -----------
extern "C" void kernel_launch(void* const* d_in, const int* in_sizes, int n_in,
                              void* d_out, int out_size) {
    const float* x  = (const float*)d_in[0];
    const void*  ei = d_in[1];
    const float* ew = (const float*)d_in[2];
    const float* W1 = (const float*)d_in[3];
    const float* b1 = (const float*)d_in[4];
    const float* W2 = (const float*)d_in[5];
    const float* b2 = (const float*)d_in[6];
    float* out = (float*)d_out;

    static cudaStream_t sB = nullptr;
    static cudaEvent_t evFork = nullptr, evPrep = nullptr;
    if (sB == nullptr) {
        cudaStreamCreateWithFlags(&sB, cudaStreamNonBlocking);
        cudaEventCreateWithFlags(&evFork, cudaEventDisableTiming);
        cudaEventCreateWithFlags(&evPrep, cudaEventDisableTiming);
    }

    const int T = 256;
    const int gN = (NN + T - 1) / T;
    const int gE = (NE + T - 1) / T;
    const int gG = (NN + 127) / 128;
    const int gA = (NN + 7) / 8;
    const int gW = (2 * DD * 32 + T - 1) / T;

    // fork: prep chain on sB
    cudaEventRecord(evFork, 0);
    cudaStreamWaitEvent(sB, evFork, 0);
    k_prep0<<<gN, T, 0, sB>>>(ei);
    k_count<<<gE, T, 0, sB>>>(ei, ew);
    k_scan1<<<NBLK, SCAN_BS, 0, sB>>>();
    k_scan3<<<NBLK, SCAN_BS, 0, sB>>>();
    k_fill<<<gE, T, 0, sB>>>(ei, ew);
    cudaEventRecord(evPrep, sB);

    // concurrent on stream0: weight split + layer-1 GEMM -> g_hh (fp16)
    k_wsplit<<<gW, T>>>(W1, W2);
    k_gemm<false><<<gG, 256>>>(x, 0);

    // join, serial tail
    cudaStreamWaitEvent(0, evPrep, 0);
    k_agg<<<gA, T>>>(b1, nullptr, 0);
    k_gemm<true><<<gG, 256>>>(nullptr, 1);
    k_agg<<<gA, T>>>(b2, out, 1);
}

// round 16
// speedup vs baseline: 1.5926x; 1.3731x over previous
#include <cuda_runtime.h>
#include <cuda_bf16.h>
#include <cuda_fp16.h>

#define NN 50000
#define NE 800000
#define DD 128
#define SCAN_BS 512
#define NBLK ((NN + SCAN_BS - 1) / SCAN_BS)   // 98

// ---------------- scratch (static __device__; referenced ONLY in device code) ----
__device__ int     g_is64;
__device__ int     g_cnt[NN];
__device__ float   g_deg[NN];
__device__ int     g_offs[NN + 1];
__device__ int     g_pos[NN];
__device__ int     g_bsum[NBLK];
__device__ int     g_src[NE];
__device__ float   g_wcsr[NE];       // full GCN norm per CSR slot
__device__ float   g_dis[NN];
__device__ __half2 g_hh[NN * 64];    // layer-1 GEMM out (X@W1), fp16
__device__ __half2 g_hh2[NN * 64];   // layer-2 GEMM out, fp16
__device__ float   g_a1[NN * DD];    // layer-1 aggregate (fp32, GEMM-2 input)
__device__ __half2 g_Wp[2][DD * 64]; // packed W: [n][k/2] half2 = (W[k][n], W[k+1][n])

// ---------------- prep0: detect dtype + zero cnt/deg ----------------
__global__ void k_prep0(const void* ei) {
    int i = blockIdx.x * blockDim.x + threadIdx.x;
    if (i < NN) { g_cnt[i] = 0; g_deg[i] = 0.0f; }
    if (blockIdx.x == 0) {
        __shared__ int bad;
        if (threadIdx.x == 0) bad = 0;
        __syncthreads();
        const long long* p = (const long long*)ei;
        for (int t = threadIdx.x; t < 1024; t += blockDim.x) {
            long long v = p[t];
            if (v < 0 || v >= NN) atomicOr(&bad, 1);
        }
        __syncthreads();
        if (threadIdx.x == 0) g_is64 = bad ? 0 : 1;
    }
}

// ---------------- count + weighted degree ----------------
__global__ void k_count(const void* ei, const float* __restrict__ ew) {
    int e = blockIdx.x * blockDim.x + threadIdx.x;
    if (e < NE) {
        int c = g_is64 ? (int)((const long long*)ei)[NE + e]
                       : ((const int*)ei)[NE + e];
        atomicAdd(&g_cnt[c], 1);
        atomicAdd(&g_deg[c], ew[e]);
    }
}

// ---------------- scan stage 1 ----------------
__global__ __launch_bounds__(SCAN_BS) void k_scan1() {
    int i = blockIdx.x * SCAN_BS + threadIdx.x;
    int lane = threadIdx.x & 31, wid = threadIdx.x >> 5;
    int v = (i < NN) ? g_cnt[i] : 0;
    int x = v;
#pragma unroll
    for (int o = 1; o < 32; o <<= 1) {
        int t = __shfl_up_sync(0xffffffffu, x, o);
        if (lane >= o) x += t;
    }
    __shared__ int wsum[16];
    if (lane == 31) wsum[wid] = x;
    __syncthreads();
    if (wid == 0) {
        int s = (lane < 16) ? wsum[lane] : 0;
#pragma unroll
        for (int o = 1; o < 16; o <<= 1) {
            int t = __shfl_up_sync(0xffffffffu, s, o);
            if (lane >= o) s += t;
        }
        if (lane < 16) wsum[lane] = s;
    }
    __syncthreads();
    int base = (wid > 0) ? wsum[wid - 1] : 0;
    if (i < NN) g_offs[i] = base + x - v;
    if (threadIdx.x == SCAN_BS - 1) g_bsum[blockIdx.x] = base + x;
}

// ---------------- scan stage 2 (fused add-back + dis) ----------------
__global__ __launch_bounds__(SCAN_BS) void k_scan3() {
    __shared__ int sbase;
    if (threadIdx.x < 32) {
        int p = 0;
        for (int j = threadIdx.x; j < blockIdx.x; j += 32) p += g_bsum[j];
#pragma unroll
        for (int o = 16; o > 0; o >>= 1) p += __shfl_down_sync(0xffffffffu, p, o);
        if (threadIdx.x == 0) sbase = p;
    }
    __syncthreads();
    int i = blockIdx.x * SCAN_BS + threadIdx.x;
    if (i < NN) {
        int off = g_offs[i] + sbase;
        g_offs[i] = off;
        g_pos[i] = off;
        g_dis[i] = rsqrtf(1.0f + g_deg[i]);
    }
    if (i == 0) g_offs[NN] = NE;
}

// ---------------- CSR fill with full norm ----------------
__global__ void k_fill(const void* ei, const float* __restrict__ ew) {
    int e = blockIdx.x * blockDim.x + threadIdx.x;
    if (e < NE) {
        int r, c;
        if (g_is64) {
            const long long* p = (const long long*)ei;
            r = (int)p[e];
            c = (int)p[NE + e];
        } else {
            const int* p = (const int*)ei;
            r = p[e];
            c = p[NE + e];
        }
        float nr = g_dis[r] * ew[e] * g_dis[c];
        int idx = atomicAdd(&g_pos[c], 1);
        g_src[idx] = r;
        g_wcsr[idx] = nr;
    }
}

// ---------------- W convert: packed fp16, B-fragment-friendly layout ----------
// g_Wp[m][n*64 + k2] = half2( W[2k2][n], W[2k2+1][n] )
__global__ void k_wconv(const float* __restrict__ W1, const float* __restrict__ W2) {
    int f = blockIdx.x * blockDim.x + threadIdx.x;   // over 2*128*64
    if (f >= 2 * DD * 64) return;
    int m = f >> 13;
    int rem = f & 8191;
    int n = rem >> 6;
    int k2 = rem & 63;
    const float* W = m ? W2 : W1;
    float lo = W[(2 * k2) * DD + n];
    float hi = W[(2 * k2 + 1) * DD + n];
    g_Wp[m][n * 64 + k2] = __floats2half2_rn(lo, hi);
}

// ---------------- fp16 MMA helper ----------------
__device__ __forceinline__ unsigned h2u(__half2 v) {
    return *reinterpret_cast<unsigned*>(&v);
}

__device__ __forceinline__ void mma_f16(float* d, const unsigned* a, const unsigned* b) {
    asm volatile("mma.sync.aligned.m16n8k16.row.col.f32.f16.f16.f32 "
                 "{%0,%1,%2,%3}, {%4,%5,%6,%7}, {%8,%9}, {%0,%1,%2,%3};"
                 : "+f"(d[0]), "+f"(d[1]), "+f"(d[2]), "+f"(d[3])
                 : "r"(a[0]), "r"(a[1]), "r"(a[2]), "r"(a[3]), "r"(b[0]), "r"(b[1]));
}

// ---------------- GEMM (fp16 MMA, fp32 accum): Hout(fp16) = X @ W[layer] ------
// BM=128, BN=128, K chunks of 32; 8 warps (4m x 2n); warp = 32 rows x 64 cols.
template<bool RELU>
__global__ __launch_bounds__(256) void k_gemm(const float* __restrict__ Xext, int layer) {
    const float* __restrict__ X = (Xext != nullptr) ? Xext : (const float*)g_a1;
    __half2* __restrict__ Hout = (layer == 0) ? (__half2*)g_hh : (__half2*)g_hh2;
    const __half2* __restrict__ Wp = g_Wp[layer];

    __shared__ __half2 sX[128][20];   // [row][k2], 16 used + 4 pad (conflict-free)
    __shared__ __half2 sW[128][20];   // [n][k2]

    const int tid = threadIdx.x;
    const int wid = tid >> 5, lane = tid & 31;
    const int g = lane >> 2, tig = lane & 3;
    const int warp_m = wid & 3, warp_n = wid >> 2;
    const int bm0 = blockIdx.x * 128;

    float acc[2][8][4];
#pragma unroll
    for (int mt = 0; mt < 2; mt++)
#pragma unroll
        for (int nt = 0; nt < 8; nt++)
#pragma unroll
            for (int c = 0; c < 4; c++) acc[mt][nt][c] = 0.0f;

#pragma unroll
    for (int c = 0; c < 4; c++) {           // k0 = 32*c
        // stage X chunk [128 rows][32 k] as half2
#pragma unroll
        for (int i = 0; i < 4; i++) {
            int f = tid + i * 256;           // 0..1023 float4 slots
            int r = f >> 3, c4 = f & 7;
            int row = bm0 + r;
            float4 v = make_float4(0.f, 0.f, 0.f, 0.f);
            if (row < NN) v = *reinterpret_cast<const float4*>(&X[row * DD + c * 32 + c4 * 4]);
            if (RELU) {
                v.x = fmaxf(v.x, 0.f); v.y = fmaxf(v.y, 0.f);
                v.z = fmaxf(v.z, 0.f); v.w = fmaxf(v.w, 0.f);
            }
            sX[r][c4 * 2]     = __floats2half2_rn(v.x, v.y);
            sX[r][c4 * 2 + 1] = __floats2half2_rn(v.z, v.w);
        }
        // stage W chunk: straight float4 copies of packed half2
#pragma unroll
        for (int i = 0; i < 2; i++) {
            int f = tid + i * 256;           // 0..511
            int n = f >> 2, q = f & 3;
            *reinterpret_cast<float4*>(&sW[n][q * 4]) =
                *reinterpret_cast<const float4*>(&Wp[n * 64 + c * 16 + q * 4]);
        }
        __syncthreads();

#pragma unroll
        for (int kk2 = 0; kk2 < 16; kk2 += 8) {
            unsigned A[2][4], B[8][2];
#pragma unroll
            for (int mt = 0; mt < 2; mt++) {
                int r0 = warp_m * 32 + mt * 16 + g;
                A[mt][0] = h2u(sX[r0][kk2 + tig]);
                A[mt][1] = h2u(sX[r0 + 8][kk2 + tig]);
                A[mt][2] = h2u(sX[r0][kk2 + tig + 4]);
                A[mt][3] = h2u(sX[r0 + 8][kk2 + tig + 4]);
            }
#pragma unroll
            for (int nt = 0; nt < 8; nt++) {
                int n = warp_n * 64 + nt * 8 + g;
                B[nt][0] = h2u(sW[n][kk2 + tig]);
                B[nt][1] = h2u(sW[n][kk2 + tig + 4]);
            }
#pragma unroll
            for (int mt = 0; mt < 2; mt++)
#pragma unroll
                for (int nt = 0; nt < 8; nt++)
                    mma_f16(acc[mt][nt], A[mt], B[nt]);
        }
        __syncthreads();
    }

    // epilogue: convert to fp16, store into [NN][64] half2 layout
#pragma unroll
    for (int mt = 0; mt < 2; mt++) {
        int r0 = bm0 + warp_m * 32 + mt * 16 + g;
        int r1 = r0 + 8;
#pragma unroll
        for (int nt = 0; nt < 8; nt++) {
            int col = warp_n * 64 + nt * 8 + tig * 2;   // even
            int h2i = col >> 1;
            if (r0 < NN)
                Hout[r0 * 64 + h2i] = __floats2half2_rn(acc[mt][nt][0], acc[mt][nt][1]);
            if (r1 < NN)
                Hout[r1 * 64 + h2i] = __floats2half2_rn(acc[mt][nt][2], acc[mt][nt][3]);
        }
    }
}

// ---------------- aggregate: warp/node CSR gather from fp16 h ----------------
// out = b + dis^2*H_i + sum nrm_j*H_src   (fp32 accumulate)
__global__ __launch_bounds__(256) void k_agg(const float* __restrict__ b,
                                             float* __restrict__ outext, int layer) {
    float* __restrict__ out = (outext != nullptr) ? outext : (float*)g_a1;
    const __half2* __restrict__ h =
        (layer == 0) ? (const __half2*)g_hh : (const __half2*)g_hh2;

    int node = blockIdx.x * 8 + (threadIdx.x >> 5);
    int lane = threadIdx.x & 31;
    if (node >= NN) return;

    const int hoff = lane * 2;   // 2 half2 = 4 cols per lane

    float s = g_dis[node];
    float s2 = s * s;
    uint2 uself = *reinterpret_cast<const uint2*>(&h[node * 64 + hoff]);
    float2 p0 = __half22float2(*reinterpret_cast<const __half2*>(&uself.x));
    float2 p1 = __half22float2(*reinterpret_cast<const __half2*>(&uself.y));
    float ax = s2 * p0.x, ay = s2 * p0.y, az = s2 * p1.x, aw = s2 * p1.y;

    int j = g_offs[node];
    int end = g_offs[node + 1];

    for (; j + 3 < end; j += 4) {
        int s0 = g_src[j],     s1 = g_src[j + 1];
        int sA = g_src[j + 2], sB = g_src[j + 3];
        float n0 = g_wcsr[j],     n1 = g_wcsr[j + 1];
        float n2 = g_wcsr[j + 2], n3 = g_wcsr[j + 3];
        uint2 u0 = *reinterpret_cast<const uint2*>(&h[s0 * 64 + hoff]);
        uint2 u1 = *reinterpret_cast<const uint2*>(&h[s1 * 64 + hoff]);
        uint2 u2 = *reinterpret_cast<const uint2*>(&h[sA * 64 + hoff]);
        uint2 u3 = *reinterpret_cast<const uint2*>(&h[sB * 64 + hoff]);
        float2 a0 = __half22float2(*reinterpret_cast<const __half2*>(&u0.x));
        float2 b0 = __half22float2(*reinterpret_cast<const __half2*>(&u0.y));
        float2 a1 = __half22float2(*reinterpret_cast<const __half2*>(&u1.x));
        float2 b1 = __half22float2(*reinterpret_cast<const __half2*>(&u1.y));
        float2 a2 = __half22float2(*reinterpret_cast<const __half2*>(&u2.x));
        float2 b2 = __half22float2(*reinterpret_cast<const __half2*>(&u2.y));
        float2 a3 = __half22float2(*reinterpret_cast<const __half2*>(&u3.x));
        float2 b3 = __half22float2(*reinterpret_cast<const __half2*>(&u3.y));
        ax += n0 * a0.x + n1 * a1.x + n2 * a2.x + n3 * a3.x;
        ay += n0 * a0.y + n1 * a1.y + n2 * a2.y + n3 * a3.y;
        az += n0 * b0.x + n1 * b1.x + n2 * b2.x + n3 * b3.x;
        aw += n0 * b0.y + n1 * b1.y + n2 * b2.y + n3 * b3.y;
    }
    for (; j < end; j++) {
        int s0 = g_src[j];
        float n0 = g_wcsr[j];
        uint2 u0 = *reinterpret_cast<const uint2*>(&h[s0 * 64 + hoff]);
        float2 a0 = __half22float2(*reinterpret_cast<const __half2*>(&u0.x));
        float2 b0 = __half22float2(*reinterpret_cast<const __half2*>(&u0.y));
        ax += n0 * a0.x; ay += n0 * a0.y; az += n0 * b0.x; aw += n0 * b0.y;
    }

    float4 bv = *reinterpret_cast<const float4*>(&b[lane * 4]);
    *reinterpret_cast<float4*>(&out[node * DD + lane * 4]) =
        make_float4(bv.x + ax, bv.y + ay, bv.z + az, bv.w + aw);
}

// ---------------- launch: prep (sB) || wconv+gemm1 (s0); serial tail -----------
extern "C" void kernel_launch(void* const* d_in, const int* in_sizes, int n_in,
                              void* d_out, int out_size) {
    const float* x  = (const float*)d_in[0];
    const void*  ei = d_in[1];
    const float* ew = (const float*)d_in[2];
    const float* W1 = (const float*)d_in[3];
    const float* b1 = (const float*)d_in[4];
    const float* W2 = (const float*)d_in[5];
    const float* b2 = (const float*)d_in[6];
    float* out = (float*)d_out;

    static cudaStream_t sB = nullptr;
    static cudaEvent_t evFork = nullptr, evPrep = nullptr;
    if (sB == nullptr) {
        cudaStreamCreateWithFlags(&sB, cudaStreamNonBlocking);
        cudaEventCreateWithFlags(&evFork, cudaEventDisableTiming);
        cudaEventCreateWithFlags(&evPrep, cudaEventDisableTiming);
    }

    const int T = 256;
    const int gN = (NN + T - 1) / T;
    const int gE = (NE + T - 1) / T;
    const int gG = (NN + 127) / 128;
    const int gA = (NN + 7) / 8;
    const int gW = (2 * DD * 64 + T - 1) / T;

    // fork: prep chain on sB
    cudaEventRecord(evFork, 0);
    cudaStreamWaitEvent(sB, evFork, 0);
    k_prep0<<<gN, T, 0, sB>>>(ei);
    k_count<<<gE, T, 0, sB>>>(ei, ew);
    k_scan1<<<NBLK, SCAN_BS, 0, sB>>>();
    k_scan3<<<NBLK, SCAN_BS, 0, sB>>>();
    k_fill<<<gE, T, 0, sB>>>(ei, ew);
    cudaEventRecord(evPrep, sB);

    // concurrent on stream0: weight convert + layer-1 GEMM -> g_hh (fp16)
    k_wconv<<<gW, T>>>(W1, W2);
    k_gemm<false><<<gG, 256>>>(x, 0);

    // join, serial tail
    cudaStreamWaitEvent(0, evPrep, 0);
    k_agg<<<gA, T>>>(b1, nullptr, 0);
    k_gemm<true><<<gG, 256>>>(nullptr, 1);
    k_agg<<<gA, T>>>(b2, out, 1);
}